// round 3
// baseline (speedup 1.0000x reference)
#include <cuda_runtime.h>
#include <cstdint>

// MessagePassing: out[src[e], k] += edge_attrs_flat[k*E + e]
// d_in[0] = edge_attrs  (float32, E*F; reference indexes flat as (F,E):
//                        val(k,e) = buf[k*E + e])
// d_in[1] = attr_idx    ((2,E) integer; dtype may be int32 or int64 — detected
//                        at runtime on-device)
// d_in[2] = n_nodes     (scalar, unused; N derived from out_size)
// d_out   = (N, F) float32, poisoned 0xAA — zeroed first.

#ifndef FEAT
#define FEAT 16
#endif

__device__ int g_idx_is_64;   // 1 if attr_idx is int64, 0 if int32

// Little-endian int64 values in [0, 2^31) have zero high words -> every odd
// int32 slot is 0. Genuine int32 node ids (uniform in [0,100000)) are ~never
// all-zero across 128 odd slots. Deterministic given the input data.
__global__ void detect_idx_dtype_kernel(const int* __restrict__ d32, int n32) {
    int is64 = 1;
    int limit = n32 < 256 ? n32 : 256;
    for (int i = 1; i < limit; i += 2) {
        if (d32[i] != 0) { is64 = 0; break; }
    }
    g_idx_is_64 = is64;
}

__global__ void zero_out_kernel_v4(float4* __restrict__ out, int n4) {
    int i = blockIdx.x * blockDim.x + threadIdx.x;
    if (i < n4) out[i] = make_float4(0.f, 0.f, 0.f, 0.f);
}

__global__ __launch_bounds__(256) void scatter_add_kernel(
    const float* __restrict__ vals,   // flat E*F, indexed [k*E + e]
    const int* __restrict__ idx32,    // attr_idx reinterpreted as int32
    float* __restrict__ out,          // (N, F)
    int E, int N)
{
    int e = blockIdx.x * blockDim.x + threadIdx.x;
    if (e >= E) return;

    // Grid-uniform branch on detected dtype.
    int s = g_idx_is_64 ? idx32[2 * (size_t)e]   // low word of int64
                        : idx32[e];              // plain int32
    if ((unsigned)s >= (unsigned)N) return;      // never crash on a bad guess

    // 16 loads: per-thread stride E, per-lane consecutive e -> fully coalesced
    // 128B lines; MLP=16 hides DRAM latency.
    float v[FEAT];
#pragma unroll
    for (int k = 0; k < FEAT; k++) {
        v[k] = __ldg(vals + (size_t)k * (size_t)E + (size_t)e);
    }

    float* o = out + (size_t)s * FEAT;   // rows 64B-aligned (F=16 floats)

    // 4x 128-bit no-return vector reductions instead of 16 scalar atomics.
#pragma unroll
    for (int j = 0; j < FEAT; j += 4) {
        asm volatile(
            "red.global.add.v4.f32 [%0], {%1, %2, %3, %4};"
            :: "l"(o + j), "f"(v[j]), "f"(v[j + 1]), "f"(v[j + 2]), "f"(v[j + 3])
            : "memory");
    }
}

extern "C" void kernel_launch(void* const* d_in, const int* in_sizes, int n_in,
                              void* d_out, int out_size) {
    const float* vals = (const float*)d_in[0];
    const int* idx32  = (const int*)d_in[1];   // raw words; dtype detected on device
    float* out        = (float*)d_out;

    int E = in_sizes[1] / 2;       // attr_idx is (2, E) in ELEMENTS (dtype-agnostic)
    int N = out_size / FEAT;       // (N, F) output

    // 1. Detect index dtype (writes g_idx_is_64). Worst case reads 256 ints.
    //    If the buffer is int64, it has 2*in_sizes[1] int32 words; if int32,
    //    in_sizes[1] words. Use the smaller bound to stay in range either way.
    detect_idx_dtype_kernel<<<1, 1>>>(idx32, in_sizes[1]);

    // 2. Zero the poisoned output (out_size = N*16, divisible by 4).
    {
        int n4 = out_size / 4;
        int threads = 256;
        int blocks = (n4 + threads - 1) / threads;
        zero_out_kernel_v4<<<blocks, threads>>>((float4*)out, n4);
    }

    // 3. Scatter-add, one thread per edge.
    {
        int threads = 256;
        int blocks = (E + threads - 1) / threads;
        scatter_add_kernel<<<blocks, threads>>>(vals, idx32, out, E, N);
    }
}

// round 5
// speedup vs baseline: 1.0118x; 1.0118x over previous
#include <cuda_runtime.h>
#include <cstdint>

// MessagePassing: out[src[e], k] += edge_attrs_flat[k*E + e]
// d_in[0] = edge_attrs  (float32, E*F; reference indexes flat as (F,E):
//                        val(k,e) = buf[k*E + e])
// d_in[1] = attr_idx    ((2,E) int32 — proven by round-2 crash under int64
//                        interpretation; row 0 = src node per edge)
// d_in[2] = n_nodes     (unused; N derived from out_size)
// d_out   = (N, F) float32, poisoned 0xAA — zeroed first.

#ifndef FEAT
#define FEAT 16
#endif
#define EDGES_PER_THREAD 2

__global__ void zero_out_kernel_v4(float4* __restrict__ out, int n4) {
    int i = blockIdx.x * blockDim.x + threadIdx.x;
    if (i < n4) out[i] = make_float4(0.f, 0.f, 0.f, 0.f);
}

__global__ __launch_bounds__(256) void scatter_add_kernel(
    const float* __restrict__ vals,   // flat E*F, indexed [k*E + e]
    const int* __restrict__ src_idx,  // row 0 of attr_idx (int32)
    float* __restrict__ out,          // (N, F)
    int E, int N)
{
    int tid = blockIdx.x * blockDim.x + threadIdx.x;

#pragma unroll
    for (int r = 0; r < EDGES_PER_THREAD; r++) {
        // Block-contiguous layout: threads of a block cover a contiguous edge
        // span; lane-consecutive e keeps every k-slice load fully coalesced.
        int e = blockIdx.x * (blockDim.x * EDGES_PER_THREAD)
              + r * blockDim.x + threadIdx.x;
        if (e >= E) continue;

        int s = src_idx[e];
        if ((unsigned)s >= (unsigned)N) continue;  // safety; never taken

        // 16 loads, per-thread stride E; MLP hides ~577-cycle DRAM latency.
        float v[FEAT];
#pragma unroll
        for (int k = 0; k < FEAT; k++) {
            v[k] = __ldg(vals + (size_t)k * (size_t)E + (size_t)e);
        }

        float* o = out + (size_t)s * FEAT;  // rows 64B-aligned (F=16 floats)

        // 4x 128-bit no-return vector reductions: 4 L2 transactions per edge.
#pragma unroll
        for (int j = 0; j < FEAT; j += 4) {
            asm volatile(
                "red.global.add.v4.f32 [%0], {%1, %2, %3, %4};"
                :: "l"(o + j), "f"(v[j]), "f"(v[j + 1]), "f"(v[j + 2]), "f"(v[j + 3])
                : "memory");
        }
    }
}

extern "C" void kernel_launch(void* const* d_in, const int* in_sizes, int n_in,
                              void* d_out, int out_size) {
    const float* vals   = (const float*)d_in[0];
    const int* src_idx  = (const int*)d_in[1];   // (2,E) int32, row 0 first
    float* out          = (float*)d_out;

    int E = in_sizes[1] / 2;     // attr_idx is (2, E)
    int N = out_size / FEAT;     // (N, F) output

    // 1. Zero the poisoned output (out_size = N*16, divisible by 4).
    {
        int n4 = out_size / 4;
        int threads = 256;
        int blocks = (n4 + threads - 1) / threads;
        zero_out_kernel_v4<<<blocks, threads>>>((float4*)out, n4);
    }

    // 2. Scatter-add, EDGES_PER_THREAD edges per thread.
    {
        int threads = 256;
        int per_block = threads * EDGES_PER_THREAD;
        int blocks = (E + per_block - 1) / per_block;
        scatter_add_kernel<<<blocks, threads>>>(vals, src_idx, out, E, N);
    }
}

// round 7
// speedup vs baseline: 1.0124x; 1.0006x over previous
#include <cuda_runtime.h>
#include <cstdint>

// MessagePassing: out[src[e], k] += edge_attrs_flat[k*E + e]
// d_in[0] = edge_attrs ((F,E)-flat float32), d_in[1] = attr_idx ((2,E) int32),
// d_in[2] = n_nodes (unused). d_out = (N,16) float32, poisoned -> zero first.

#ifndef FEAT
#define FEAT 16
#endif
#define EPT 4   // edges per thread (LDG.128 over 4 consecutive e)

__global__ void zero_out_kernel_v4(float4* __restrict__ out, int n4) {
    int i = blockIdx.x * blockDim.x + threadIdx.x;
    if (i < n4) out[i] = make_float4(0.f, 0.f, 0.f, 0.f);
}

__device__ __forceinline__ float f4_comp(const float4& v, int j) {
    // j is compile-time after unroll.
    return j == 0 ? v.x : j == 1 ? v.y : j == 2 ? v.z : v.w;
}

__device__ __forceinline__ void red_row_v4(float* o, float a, float b, float c, float d) {
    asm volatile(
        "red.global.add.v4.f32 [%0], {%1, %2, %3, %4};"
        :: "l"(o), "f"(a), "f"(b), "f"(c), "f"(d)
        : "memory");
}

__global__ __launch_bounds__(256) void scatter_add_kernel(
    const float* __restrict__ vals,   // flat E*F, indexed [k*E + e]
    const int*  __restrict__ src_idx, // row 0 of attr_idx (int32)
    float* __restrict__ out,          // (N, F)
    int E, int N)
{
    size_t t  = (size_t)blockIdx.x * blockDim.x + threadIdx.x;
    size_t e0 = t * EPT;

    if (e0 + (EPT - 1) < (size_t)E) {
        // ---- Fast path: ALL loads first (17 independent LDG.128, 272B in
        //      flight per thread), then all REDs.
        int4 s4 = __ldg((const int4*)(src_idx + e0));

        float4 vv[FEAT];                 // vv[k] = feature k of edges e0..e0+3
#pragma unroll
        for (int k = 0; k < FEAT; k++) {
            vv[k] = __ldg((const float4*)(vals + (size_t)k * (size_t)E + e0));
        }

        int ss[EPT] = { s4.x, s4.y, s4.z, s4.w };

#pragma unroll
        for (int j = 0; j < EPT; j++) {
            int s = ss[j];
            if ((unsigned)s >= (unsigned)N) continue;   // safety; never taken
            float* o = out + (size_t)s * FEAT;          // 64B-aligned row
#pragma unroll
            for (int k = 0; k < FEAT; k += 4) {
                red_row_v4(o + k,
                           f4_comp(vv[k + 0], j), f4_comp(vv[k + 1], j),
                           f4_comp(vv[k + 2], j), f4_comp(vv[k + 3], j));
            }
        }
    } else {
        // ---- Tail: scalar per edge (E divisible by 1024 -> normally unused).
        for (size_t e = e0; e < (size_t)E && e < e0 + EPT; e++) {
            int s = src_idx[e];
            if ((unsigned)s >= (unsigned)N) continue;
            float v[FEAT];
#pragma unroll
            for (int k = 0; k < FEAT; k++)
                v[k] = __ldg(vals + (size_t)k * (size_t)E + e);
            float* o = out + (size_t)s * FEAT;
#pragma unroll
            for (int k = 0; k < FEAT; k += 4)
                red_row_v4(o + k, v[k], v[k + 1], v[k + 2], v[k + 3]);
        }
    }
}

extern "C" void kernel_launch(void* const* d_in, const int* in_sizes, int n_in,
                              void* d_out, int out_size) {
    const float* vals  = (const float*)d_in[0];
    const int* src_idx = (const int*)d_in[1];   // (2,E) int32, row 0 first
    float* out         = (float*)d_out;

    int E = in_sizes[1] / 2;     // attr_idx is (2, E)
    int N = out_size / FEAT;     // (N, F) output

    // 1. Zero the poisoned output (out_size divisible by 4).
    {
        int n4 = out_size / 4;
        int threads = 256;
        int blocks = (n4 + threads - 1) / threads;
        zero_out_kernel_v4<<<blocks, threads>>>((float4*)out, n4);
    }

    // 2. Scatter-add, 4 edges per thread via 128-bit loads.
    {
        int threads = 256;
        int per_block = threads * EPT;
        int blocks = (E + per_block - 1) / per_block;
        scatter_add_kernel<<<blocks, threads>>>(vals, src_idx, out, E, N);
    }
}

// round 13
// speedup vs baseline: 1.6260x; 1.6061x over previous
#include <cuda_runtime.h>
#include <cstdint>

// MessagePassing: out[src[e], k] += edge_attrs_flat[k*E + e]
// d_in[0] = edge_attrs ((F,E)-flat float32), d_in[1] = attr_idx ((2,E) int32),
// d_in[2] = n_nodes (unused). d_out = (N,16) float32, poisoned -> zero first.
//
// Lane mapping (the experiment): 4 lanes cooperate per edge so the red.v4
// lane requests of a group land in ONE 64B output row -> they coalesce in
// L1tex instead of generating 32 scattered wavefronts per RED instruction.

#ifndef FEAT
#define FEAT 16
#endif

__global__ void zero_out_kernel_v4(float4* __restrict__ out, int n4) {
    int i = blockIdx.x * blockDim.x + threadIdx.x;
    if (i < n4) out[i] = make_float4(0.f, 0.f, 0.f, 0.f);
}

__device__ __forceinline__ float f4_comp(const float4& v, int j) {
    return j == 0 ? v.x : j == 1 ? v.y : j == 2 ? v.z : v.w;
}

__device__ __forceinline__ int i4_comp(const int4& v, int j) {
    return j == 0 ? v.x : j == 1 ? v.y : j == 2 ? v.z : v.w;
}

__device__ __forceinline__ void red_v4(float* o, float a, float b, float c, float d) {
    asm volatile(
        "red.global.add.v4.f32 [%0], {%1, %2, %3, %4};"
        :: "l"(o), "f"(a), "f"(b), "f"(c), "f"(d)
        : "memory");
}

// One warp handles 32 consecutive edges per iteration.
//   lane l: q = l&3  -> feature quad [4q, 4q+4)
//           g = l>>2 -> edges [eb, eb+4), eb = warp_base + 4g
__global__ __launch_bounds__(256) void scatter_add_kernel(
    const float* __restrict__ vals,   // flat E*F, indexed [k*E + e]
    const int*  __restrict__ src_idx, // row 0 of attr_idx (int32)
    float* __restrict__ out,          // (N, F)
    int E, int N)
{
    int lane = threadIdx.x & 31;
    int warp_global = (blockIdx.x * (blockDim.x >> 5)) + (threadIdx.x >> 5);
    int q = lane & 3;
    int g = lane >> 2;

    size_t warp_base = (size_t)warp_global * 32;
    size_t eb = warp_base + (size_t)g * 4;

    if (warp_base + 31 < (size_t)E) {
        // ---- Fast path. 5 independent LDG.128 per lane, then 4 coalesced REDs.
        int4 s4 = __ldg((const int4*)(src_idx + eb));   // src of edges eb..eb+3

        // f4[i] = feature (4q+i) of edges eb..eb+3
        float4 f4[4];
#pragma unroll
        for (int i = 0; i < 4; i++) {
            f4[i] = __ldg((const float4*)(vals + (size_t)(4 * q + i) * (size_t)E + eb));
        }

#pragma unroll
        for (int j = 0; j < 4; j++) {                   // edge eb+j
            int s = i4_comp(s4, j);
            if ((unsigned)s >= (unsigned)N) continue;   // safety; never taken
            // The 4 lanes of this group write quads 0..3 of the SAME row:
            // addresses s*64B + q*16B -> coalesce to one 64B span.
            float* o = out + (size_t)s * FEAT + 4 * q;
            red_v4(o, f4_comp(f4[0], j), f4_comp(f4[1], j),
                      f4_comp(f4[2], j), f4_comp(f4[3], j));
        }
    } else {
        // ---- Tail (E divisible by 256 -> normally unused): lane-per-edge scalar.
        size_t e = warp_base + lane;
        if (e < (size_t)E) {
            int s = src_idx[e];
            if ((unsigned)s < (unsigned)N) {
                float v[FEAT];
#pragma unroll
                for (int k = 0; k < FEAT; k++)
                    v[k] = __ldg(vals + (size_t)k * (size_t)E + e);
                float* o = out + (size_t)s * FEAT;
#pragma unroll
                for (int k = 0; k < FEAT; k += 4)
                    red_v4(o + k, v[k], v[k + 1], v[k + 2], v[k + 3]);
            }
        }
    }
}

extern "C" void kernel_launch(void* const* d_in, const int* in_sizes, int n_in,
                              void* d_out, int out_size) {
    const float* vals  = (const float*)d_in[0];
    const int* src_idx = (const int*)d_in[1];   // (2,E) int32, row 0 first
    float* out         = (float*)d_out;

    int E = in_sizes[1] / 2;     // attr_idx is (2, E)
    int N = out_size / FEAT;     // (N, F) output

    // 1. Zero the poisoned output.
    {
        int n4 = out_size / 4;
        int threads = 256;
        int blocks = (n4 + threads - 1) / threads;
        zero_out_kernel_v4<<<blocks, threads>>>((float4*)out, n4);
    }

    // 2. Scatter-add: 32 edges per warp, 4 lanes per edge.
    {
        int threads = 256;                    // 8 warps -> 256 edges per block
        int edges_per_block = (threads / 32) * 32;
        int blocks = (E + edges_per_block - 1) / edges_per_block;
        scatter_add_kernel<<<blocks, threads>>>(vals, src_idx, out, E, N);
    }
}